// round 12
// baseline (speedup 1.0000x reference)
#include <cuda_runtime.h>
#include <cuda_fp16.h>
#include <cstdint>

// Ordered_GCN: B=64, N=207, K=32, C=8, D_IN=64, D_OUT=64, tokens = 13248.
// R11 = R10 (HMMA GEMM, fp16 means/weights, fp32 accum, cp.async.bulk ring)
// with the per-chunk lockstep removed:
//  - per-slot "full" mbarrier (tx-count) gates consumers per warp
//  - per-slot "consumed" mbarrier (32 warp arrivals) gates producer refill
//  - only TWO __syncthreads per batch (pre-MMA, post-ldmatrix); epilogue
//    (tanh+stores) overlaps next batch's scatter
// total = 13248 = 828 * 16 exactly -> no tail guards on the batch path.

#define KNB   32
#define NTHR  1024
#define CHUNK 4
#define TB    16
#define RING  4
#define DEPTH 3
#define TOKEN_IN  2048
#define TOKEN_OUT 512

#define WIN_SLOT  32768                          // 4 tokens * 8KB
#define OFF_A     (RING * WIN_SLOT)              // 131072
#define A_BUF     16384                          // 128 rows x 128B
#define OFF_W     (OFF_A + A_BUF)                // 147456
#define OFF_IDX   (OFF_W + 65536)                // 212992
#define IDX_SLOT  512                            // 4 tokens * 128B
#define OFF_FULL  (OFF_IDX + RING * IDX_SLOT)    // 215040  (4 x 8B)
#define OFF_CONS  (OFF_FULL + 32)                // +32     (4 x 8B)
#define SMEM_BYTES (OFF_CONS + 32 + 1024)

#define SW128(o) ((o) ^ (((o) >> 3) & 0x70))

__device__ __forceinline__ float fast_tanh(float z) {
    float e = __expf(2.0f * z);
    return 1.0f - __fdividef(2.0f, e + 1.0f);
}

#define MBAR_INIT(addr, cnt) \
    asm volatile("mbarrier.init.shared.b64 [%0], %1;" :: "r"(addr), "r"(cnt) : "memory")
#define MBAR_ARRIVE(addr) \
    asm volatile("mbarrier.arrive.shared.b64 _, [%0];" :: "r"(addr) : "memory")
#define MBAR_WAIT(addr, par) do {                                              \
    uint32_t _m = (addr), _p = (par), _d;                                      \
    asm volatile("{\n\t.reg .pred p;\n\t"                                      \
        "mbarrier.try_wait.parity.acquire.cta.shared::cta.b64 p, [%1], %2;\n\t"\
        "selp.b32 %0, 1, 0, p;\n\t}" : "=r"(_d) : "r"(_m), "r"(_p) : "memory");\
    if (!_d) {                                                                 \
        asm volatile("{\n\t.reg .pred P1;\n\t"                                 \
        "WL%=:\n\t"                                                            \
        "mbarrier.try_wait.parity.acquire.cta.shared::cta.b64 P1, [%0], %1, 0x989680;\n\t" \
        "@P1 bra.uni WD%=;\n\t"                                                \
        "bra.uni WL%=;\n\t"                                                    \
        "WD%=:\n\t}" :: "r"(_m), "r"(_p) : "memory");                          \
    }                                                                          \
} while (0)

__global__ void __launch_bounds__(NTHR, 1)
ordered_gcn_kernel(const int* __restrict__ idx,
                   const float* __restrict__ win,
                   const float* __restrict__ W,
                   float* __restrict__ out,
                   int total, int nbatch)
{
    extern __shared__ char raw[];
    char* base = (char*)(((uintptr_t)raw + 1023) & ~(uintptr_t)1023);
    const uint32_t sb = (uint32_t)__cvta_generic_to_shared(base);
    char* W_s = base + OFF_W;

    const int tid  = threadIdx.x;
    const int lane = tid & 31;
    const int w    = tid >> 5;
    const int grid = gridDim.x;

    // ---- one-thread bulk staging of a 4-token chunk into a ring slot ----
    auto issue_chunk = [&](int seq) {
        int bb = blockIdx.x + (seq >> 2) * grid;
        if (bb >= nbatch) return;
        int slot = seq & (RING - 1);
        uint32_t mbar = sb + OFF_FULL + slot * 8;
        size_t cb = (size_t)bb * TB + (seq & 3) * CHUNK;
        asm volatile("mbarrier.arrive.expect_tx.shared.b64 _, [%0], %1;"
                     :: "r"(mbar), "r"(33280u) : "memory");
        asm volatile(
            "cp.async.bulk.shared::cta.global.mbarrier::complete_tx::bytes "
            "[%0], [%1], %2, [%3];"
            :: "r"(sb + slot * WIN_SLOT), "l"((const char*)win + cb * 8192),
               "r"((uint32_t)WIN_SLOT), "r"(mbar) : "memory");
        asm volatile(
            "cp.async.bulk.shared::cta.global.mbarrier::complete_tx::bytes "
            "[%0], [%1], %2, [%3];"
            :: "r"(sb + OFF_IDX + slot * IDX_SLOT), "l"((const char*)idx + cb * 128),
               "r"((uint32_t)IDX_SLOT), "r"(mbar) : "memory");
    };

    if (tid == 0) {
        #pragma unroll
        for (int s = 0; s < RING; s++) {
            MBAR_INIT(sb + OFF_FULL + s * 8, 1);
            MBAR_INIT(sb + OFF_CONS + s * 8, 32);
        }
    }
    __syncthreads();                 // mbar init visible before any wait/issue
    if (tid == 0) { issue_chunk(0); issue_chunk(1); issue_chunk(2); }

    // ---- convert W fp32 gmem -> fp16 smem (SW128 rows of 128B) ----
    for (int i = tid; i < 16384; i += NTHR) {        // fp16x2 pairs
        int c = i >> 11, o = (i >> 5) & 63, dp = i & 31;
        float2 v = ((const float2*)W)[i];
        *(__half2*)(W_s + c * 8192 + SW128(o * 128 + dp * 4)) =
            __floats2half2_rn(v.x, v.y);
    }

    // roles (both decompose the 32 warps the same way)
    const int cs = w & 7, js = w >> 3;   // scatter: class cs, token js in chunk
    const int cm = w & 7, nq = w >> 3;   // mma: class cm, n-quarter nq

    char* A_s = base + OFF_A;
    const uint32_t abase = sb + OFF_A;
    const uint32_t wbase = sb + OFF_W + cm * 8192;

    int bi = 0;
    for (int b = blockIdx.x; b < nbatch; b += grid, ++bi) {
        // ---- 4 chunks: scatter class-means into A (warps drift freely) ----
        #pragma unroll
        for (int q = 0; q < 4; q++) {
            const int seq  = bi * 4 + q;
            const int slot = seq & (RING - 1);
            MBAR_WAIT(sb + OFF_FULL + slot * 8, (uint32_t)((seq >> 2) & 1));

            const int* ib = (const int*)(base + OFF_IDX + slot * IDX_SLOT) + js * KNB;
            int my = ib[lane];
            unsigned mask = __ballot_sync(0xffffffffu, my == cs);
            int cnt = __popc(mask);
            float rc = __fdividef(1.0f, (float)(cnt > 0 ? cnt : 1));
            const float2* rows =
                (const float2*)(base + slot * WIN_SLOT + js * 8192);
            float s0 = 0.0f, s1 = 0.0f;
            unsigned m = mask;
            while (m) {
                int k = __ffs(m) - 1;
                m &= m - 1;
                float2 v = rows[k * 32 + lane];
                s0 += v.x; s1 += v.y;
            }
            int row = cs * 16 + q * CHUNK + js;      // [class][token-in-batch]
            *(__half2*)(A_s + SW128(row * 128 + lane * 4)) =
                __floats2half2_rn(s0 * rc, s1 * rc);

            // this warp is done reading slot -> consumed arrival
            if (lane == 0) MBAR_ARRIVE(sb + OFF_CONS + slot * 8);

            // producer: refill DEPTH ahead, gated on that slot's consumers
            if (tid == 0) {
                int rseq = seq + DEPTH;
                int rslot = rseq & (RING - 1);
                if (rseq >= RING)
                    MBAR_WAIT(sb + OFF_CONS + rslot * 8,
                              (uint32_t)(((rseq >> 2) - 1) & 1));
                issue_chunk(rseq);
            }
        }
        __syncthreads();                 // B1: A complete (W_s too, 1st batch)

        // ---- MMA: M=16 tokens, N=16 (quarter), K=64, 4 k-steps ----
        float acc[2][4] = {};
        #pragma unroll
        for (int kk = 0; kk < 4; kk++) {
            uint32_t a0, a1, a2, a3;
            {
                unsigned row = cm * 16 + (lane & 15);
                unsigned off = SW128(row * 128 + kk * 32 + ((lane >> 4) << 4));
                asm volatile(
                    "ldmatrix.sync.aligned.m8n8.x4.shared.b16 {%0,%1,%2,%3}, [%4];"
                    : "=r"(a0), "=r"(a1), "=r"(a2), "=r"(a3) : "r"(abase + off));
            }
            #pragma unroll
            for (int nt = 0; nt < 2; nt++) {
                uint32_t b0, b1;
                // W stored [n][k] row-major == col-major KxN -> NON-trans load
                unsigned nrow = nq * 16 + nt * 8 + (lane & 7);
                unsigned off  = SW128(nrow * 128 + kk * 32 + ((lane >> 3) & 1) * 16);
                asm volatile(
                    "ldmatrix.sync.aligned.m8n8.x2.shared.b16 {%0,%1}, [%2];"
                    : "=r"(b0), "=r"(b1) : "r"(wbase + off));
                asm volatile(
                    "mma.sync.aligned.m16n8k16.row.col.f32.f16.f16.f32 "
                    "{%0,%1,%2,%3}, {%4,%5,%6,%7}, {%8,%9}, {%0,%1,%2,%3};"
                    : "+f"(acc[nt][0]), "+f"(acc[nt][1]),
                      "+f"(acc[nt][2]), "+f"(acc[nt][3])
                    : "r"(a0), "r"(a1), "r"(a2), "r"(a3), "r"(b0), "r"(b1));
            }
        }
        __syncthreads();                 // B2: A reads done -> next batch may write

        // ---- epilogue (overlaps next batch's scatter in other warps) ----
        const int tb = b * TB;
        #pragma unroll
        for (int nt = 0; nt < 2; nt++) {
            int col = cm * 64 + nq * 16 + nt * 8 + (lane & 3) * 2;
            int r0 = tb + (lane >> 2), r1 = r0 + 8;
            float2 v0 = { fast_tanh(acc[nt][0]), fast_tanh(acc[nt][1]) };
            float2 v1 = { fast_tanh(acc[nt][2]), fast_tanh(acc[nt][3]) };
            __stcs((float2*)(out + (size_t)r0 * TOKEN_OUT + col), v0);
            __stcs((float2*)(out + (size_t)r1 * TOKEN_OUT + col), v1);
        }
    }
}

extern "C" void kernel_launch(void* const* d_in, const int* in_sizes, int n_in,
                              void* d_out, int out_size) {
    const int*   idx = (const int*)d_in[0];   // [B,N,K] int32
    const float* win = (const float*)d_in[1]; // [B,N,K,D_IN] f32
    const float* W   = (const float*)d_in[2]; // [C,D_OUT,D_IN] f32
    float* out = (float*)d_out;               // [B,N,C,D_OUT] f32

    const int total  = in_sizes[0] / KNB;     // 13248
    const int nbatch = total / TB;            // 828 (exact)

    static int smem_set = 0;
    if (!smem_set) {
        cudaFuncSetAttribute(ordered_gcn_kernel,
                             cudaFuncAttributeMaxDynamicSharedMemorySize,
                             SMEM_BYTES);
        smem_set = 1;
    }

    int sms = 148, dev = 0;
    cudaGetDevice(&dev);
    cudaDeviceGetAttribute(&sms, cudaDevAttrMultiProcessorCount, dev);
    int grid = (sms < nbatch) ? sms : nbatch;

    ordered_gcn_kernel<<<grid, NTHR, SMEM_BYTES>>>(idx, win, W, out, total, nbatch);
}